// round 14
// baseline (speedup 1.0000x reference)
#include <cuda_runtime.h>
#include <cuda_fp16.h>

// Problem constants (fixed by the dataset)
#define NN   100000
#define EE   3200000
#define INF_ 128
#define HID_ 16
#define NC_  64
#define SLOT 128     // max in-degree bucket (Poisson(32): P(>128) ~ 1e-50)

// ---------------- scratch (static device allocations only) ----------------
// All state is restored by end of each kernel_launch sequence so graph
// replays are deterministic: g_cnt zeroed by k_agg2f after last read,
// g_Sacc/g_done zeroed by the epilogue block.
__device__ int     g_done;
__device__ int     g_cnt[NN];             // in-degree counters (zero at entry)
__device__ int     g_slots[NN * SLOT];    // per-destination source buckets
__device__ __half2 g_h1s[NN * 8];         // (x@W1)*dinv, fp16 pairs (32B/node)
__device__ __half2 g_o1s[NN * 8];         // relu(layer1)*dinv, fp16 pairs
__device__ float   g_Sacc[NC_ * 64];      // pooled colsum, 256B stride spreads L2 slices

// ---------------- kernels ----------------

// Build bucket adjacency in ONE pass: idx = atomicAdd(cnt[col]), slot write.
// dtype (int32 vs int64) detected per block from the first 128 bytes:
// int64 values < 2^31 have every odd int32 word == 0.
__global__ void k_fill(const void* __restrict__ ei, int e, int n) {
    __shared__ int sIs64;
    int tid = threadIdx.x;
    if (tid == 0) sIs64 = 1;
    __syncthreads();
    if (tid < 64 && ((const unsigned int*)ei)[2 * tid + 1] != 0u) sIs64 = 0;
    __syncthreads();
    int is64 = sIs64;

    int i = (blockIdx.x * blockDim.x + tid) * 4;
    if (i >= e) return;
    int r[4], c[4], m = (e - i < 4) ? (e - i) : 4;
    if (is64) {
        const long long* row = (const long long*)ei;
        const long long* col = row + e;
        for (int j = 0; j < m; j++) { r[j] = (int)row[i + j]; c[j] = (int)col[i + j]; }
    } else {
        const int* row = (const int*)ei;
        const int* col = row + e;
        if (m == 4) {
            int4 r4 = *(const int4*)(row + i);
            int4 c4 = *(const int4*)(col + i);
            r[0] = r4.x; r[1] = r4.y; r[2] = r4.z; r[3] = r4.w;
            c[0] = c4.x; c[1] = c4.y; c[2] = c4.z; c[3] = c4.w;
        } else {
            for (int j = 0; j < m; j++) { r[j] = row[i + j]; c[j] = col[i + j]; }
        }
    }
    for (int j = 0; j < m; j++) {
        if ((unsigned)c[j] < (unsigned)n && (unsigned)r[j] < (unsigned)n) {
            int p = atomicAdd(&g_cnt[c[j]], 1);
            if (p < SLOT) g_slots[c[j] * SLOT + p] = r[j];
        }
    }
}

// h1s[n][f] = (x[n] . W1[:,f]) * rsqrt(deg[n]+1), stored as half2 pairs.
__global__ void k_gemm1(const float* __restrict__ x,
                        const float* __restrict__ W1, int n) {
    __shared__ __align__(16) float Ws[INF_ * HID_];   // 8 KB, [k][f]
    __shared__ float Xs[128 * 65];
    int tid = threadIdx.x;
    int fg = tid >> 6;          // 0..3  (features fg*4 .. fg*4+3)
    int q  = tid & 63;
    int base = blockIdx.x * 128;

    for (int i = tid; i < INF_ * HID_; i += 256) Ws[i] = W1[i];

    float4 a0 = {0.f, 0.f, 0.f, 0.f};
    float4 a1 = {0.f, 0.f, 0.f, 0.f};

    for (int kc = 0; kc < 2; kc++) {
        __syncthreads();
        for (int idx = tid; idx < 128 * 16; idx += 256) {
            int row = idx >> 4, c4 = idx & 15;
            int node = base + row;
            float4 v = {0.f, 0.f, 0.f, 0.f};
            if (node < n) v = *(const float4*)&x[node * INF_ + kc * 64 + c4 * 4];
            float* dst = &Xs[row * 65 + c4 * 4];
            dst[0] = v.x; dst[1] = v.y; dst[2] = v.z; dst[3] = v.w;
        }
        __syncthreads();
#pragma unroll 8
        for (int k = 0; k < 64; k++) {
            float xv0 = Xs[q * 65 + k];
            float xv1 = Xs[(q + 64) * 65 + k];
            float4 w4 = *(const float4*)&Ws[(kc * 64 + k) * HID_ + fg * 4];
            a0.x = fmaf(xv0, w4.x, a0.x); a0.y = fmaf(xv0, w4.y, a0.y);
            a0.z = fmaf(xv0, w4.z, a0.z); a0.w = fmaf(xv0, w4.w, a0.w);
            a1.x = fmaf(xv1, w4.x, a1.x); a1.y = fmaf(xv1, w4.y, a1.y);
            a1.z = fmaf(xv1, w4.z, a1.z); a1.w = fmaf(xv1, w4.w, a1.w);
        }
    }
    int n0 = base + q, n1 = base + q + 64;
    if (n0 < n) {
        float d = rsqrtf((float)(g_cnt[n0] + 1));
        g_h1s[n0 * 8 + fg * 2]     = __floats2half2_rn(a0.x * d, a0.y * d);
        g_h1s[n0 * 8 + fg * 2 + 1] = __floats2half2_rn(a0.z * d, a0.w * d);
    }
    if (n1 < n) {
        float d = rsqrtf((float)(g_cnt[n1] + 1));
        g_h1s[n1 * 8 + fg * 2]     = __floats2half2_rn(a1.x * d, a1.y * d);
        g_h1s[n1 * 8 + fg * 2 + 1] = __floats2half2_rn(a1.z * d, a1.w * d);
    }
}

// Layer-1 aggregate + relu, pre-scaled for layer 2:
// o1s[n][f] = relu(dinv*(h1s[n]+sum_r h1s[r]) + b1) * dinv
// Warp per node: 32 lanes = 4 edge-groups x 8 feature-lanes (half2 each).
__global__ void k_agg1f(const float* __restrict__ b1, int n) {
    int tid = threadIdx.x, lane = tid & 31, w = tid >> 5;
    int eg = lane >> 3, t = lane & 7;
    int node = blockIdx.x * 8 + w;
    if (node >= n) return;
    int cnt = g_cnt[node];
    if (cnt > SLOT) cnt = SLOT;
    float2 s = {0.f, 0.f};
    if (eg == 0) s = __half22float2(g_h1s[node * 8 + t]);   // self loop
    const int* slots = &g_slots[node * SLOT];
    for (int i = eg; i < cnt; i += 4) {
        int r = __ldg(&slots[i]);
        float2 v = __half22float2(g_h1s[r * 8 + t]);
        s.x += v.x; s.y += v.y;
    }
    s.x += __shfl_xor_sync(0xffffffffu, s.x, 8);
    s.y += __shfl_xor_sync(0xffffffffu, s.y, 8);
    s.x += __shfl_xor_sync(0xffffffffu, s.x, 16);
    s.y += __shfl_xor_sync(0xffffffffu, s.y, 16);
    if (lane < 8) {
        float d = rsqrtf((float)(cnt + 1));
        float2 bb = ((const float2*)b1)[t];
        float ox = fmaxf(fmaf(s.x, d, bb.x), 0.f) * d;
        float oy = fmaxf(fmaf(s.y, d, bb.y), 0.f) * d;
        g_o1s[node * 8 + t] = __floats2half2_rn(ox, oy);
    }
}

// Layer-2 fully fused: 16-dim aggregate (A commutes with W2), 16->64 GEMM +
// bias + relu accumulated into the global pool; last block does the epilogue
// and restores all persistent state (g_cnt zeroed per node after last read).
__global__ void k_agg2f(const float* __restrict__ b2,
                        const float* __restrict__ W2,
                        const float* __restrict__ fcW,
                        const float* __restrict__ fcb,
                        float* __restrict__ out, int n) {
    __shared__ __align__(16) float Ws[HID_ * NC_];   // 4 KB, [j][k]
    __shared__ float A16[8 * 17];
    __shared__ float red[8 * 66];
    int tid = threadIdx.x, lane = tid & 31, w = tid >> 5;
    for (int i = tid; i < HID_ * NC_; i += 256) Ws[i] = W2[i];

    int eg = lane >> 3, tA = lane & 7;       // phase-A mapping
    int wB = tid >> 5, cB = tid & 31;        // phase-B: node slot, col pair
    float2 bb = ((const float2*)b2)[cB];
    float2 acc = {0.f, 0.f};

    int ntiles = (n + 7) / 8;

    for (int tile = blockIdx.x; tile < ntiles; tile += gridDim.x) {
        __syncthreads();                     // protect A16 reuse
        int node = tile * 8 + w;
        if (node < n) {
            int cnt = g_cnt[node];
            if (cnt > SLOT) cnt = SLOT;
            __syncwarp();
            if (lane == 0) g_cnt[node] = 0;  // restore for next graph replay
            float2 s = {0.f, 0.f};
            if (eg == 0) s = __half22float2(g_o1s[node * 8 + tA]);
            const int* slots = &g_slots[node * SLOT];
            for (int i = eg; i < cnt; i += 4) {
                int r = __ldg(&slots[i]);
                float2 v = __half22float2(g_o1s[r * 8 + tA]);
                s.x += v.x; s.y += v.y;
            }
            s.x += __shfl_xor_sync(0xffffffffu, s.x, 8);
            s.y += __shfl_xor_sync(0xffffffffu, s.y, 8);
            s.x += __shfl_xor_sync(0xffffffffu, s.x, 16);
            s.y += __shfl_xor_sync(0xffffffffu, s.y, 16);
            if (lane < 8) {
                float d = rsqrtf((float)(cnt + 1));
                A16[w * 17 + 2 * tA]     = s.x * d;
                A16[w * 17 + 2 * tA + 1] = s.y * d;
            }
        }
        __syncthreads();
        int node2 = tile * 8 + wB;
        if (node2 < n) {
            float2 p = bb;
#pragma unroll
            for (int j = 0; j < HID_; j++) {
                float o = A16[wB * 17 + j];
                float2 w2 = *(const float2*)&Ws[j * NC_ + 2 * cB];
                p.x = fmaf(o, w2.x, p.x);
                p.y = fmaf(o, w2.y, p.y);
            }
            acc.x += fmaxf(p.x, 0.f);
            acc.y += fmaxf(p.y, 0.f);
        }
    }

    // block-level pool reduce
    __syncthreads();
    red[wB * 66 + 2 * cB]     = acc.x;
    red[wB * 66 + 2 * cB + 1] = acc.y;
    __syncthreads();
    if (tid < 64) {
        float tot = 0.f;
#pragma unroll
        for (int i = 0; i < 8; i++) tot += red[i * 66 + tid];
        atomicAdd(&g_Sacc[tid * 64], tot);
    }

    // last block computes the epilogue and restores g_Sacc / g_done
    __threadfence();
    __shared__ int amLast;
    if (tid == 0) amLast = (atomicAdd(&g_done, 1) == gridDim.x - 1);
    __syncthreads();
    if (amLast && tid == 0) {
        float nf = (float)n;
        float p0 = nf * fcb[0], p1 = nf * fcb[1];
        for (int k = 0; k < NC_; k++) {
            float sv = g_Sacc[k * 64];
            g_Sacc[k * 64] = 0.f;
            p0 = fmaf(sv, fcW[k * 2 + 0], p0);
            p1 = fmaf(sv, fcW[k * 2 + 1], p1);
        }
        g_done = 0;
        float m = fmaxf(p0, p1);
        float l = m + logf(expf(p0 - m) + expf(p1 - m));
        out[0] = p0 - l;
        out[1] = p1 - l;
    }
}

// ---------------- launcher ----------------
extern "C" void kernel_launch(void* const* d_in, const int* in_sizes, int n_in,
                              void* d_out, int out_size) {
    const float* x   = (const float*)d_in[0];
    const void*  ei  = (const void*)d_in[1];
    const float* W1  = (const float*)d_in[2];
    const float* b1  = (const float*)d_in[3];
    const float* W2  = (const float*)d_in[4];
    const float* b2  = (const float*)d_in[5];
    const float* fcW = (const float*)d_in[6];
    const float* fcb = (const float*)d_in[7];
    float* out = (float*)d_out;

    int n = in_sizes[0] / INF_;   // 100000
    int e = in_sizes[1] / 2;      // 3200000
    if (n > NN) n = NN;
    if (e > EE) e = EE;

    int nbEdge4 = (e + 1023) / 1024;   // 4 edges/thread, 256 threads

    k_fill  <<<nbEdge4, 256>>>(ei, e, n);
    k_gemm1 <<<(n + 127) / 128, 256>>>(x, W1, n);
    k_agg1f <<<(n + 7) / 8, 256>>>(b1, n);
    k_agg2f <<<1184, 256>>>(b2, W2, fcW, fcb, out, n);
}

// round 17
// speedup vs baseline: 1.0875x; 1.0875x over previous
#include <cuda_runtime.h>
#include <cuda_fp16.h>

// Problem constants (fixed by the dataset)
#define NN   100000
#define EE   3200000
#define INF_ 128
#define HID_ 16
#define NC_  64

// ---------------- scratch (static device allocations only) ----------------
// g_cnt / g_Sacc / g_done are restored by k_agg2f so every kernel_launch
// (incl. graph replays) starts from the same state. Statics begin zeroed.
__device__ int     g_done;
__device__ int     g_cnt[NN];          // in-degree counters (zero at entry)
__device__ int     g_off[NN + 1];
__device__ int     g_cur[NN];
__device__ float   g_dinv[NN];
__device__ int     g_rows[EE];         // packed CSR-by-destination source list
__device__ __half2 g_h1s[NN * 8];      // (x@W1)*dinv, fp16 pairs (32B/node)
__device__ __half2 g_o1s[NN * 8];      // relu(layer1)*dinv, fp16 pairs
__device__ float   g_Sacc[NC_ * 64];   // pooled colsum, 256B stride spreads L2 slices
__device__ int     g_bsum[128];

// ---------------- kernels ----------------

// Count in-degrees. dtype (int32 vs int64) detected per block from the first
// 128 bytes: int64 values < 2^31 have every odd int32 word == 0.
__global__ void k_count(const void* __restrict__ ei, int e, int n) {
    __shared__ int sIs64;
    int tid = threadIdx.x;
    if (tid == 0) sIs64 = 1;
    __syncthreads();
    if (tid < 64 && ((const unsigned int*)ei)[2 * tid + 1] != 0u) sIs64 = 0;
    __syncthreads();
    int is64 = sIs64;

    int i = (blockIdx.x * blockDim.x + tid) * 4;
    if (i >= e) return;
    if (is64) {
        const long long* col = (const long long*)ei + e;
#pragma unroll
        for (int j = 0; j < 4; j++)
            if (i + j < e) {
                int c = (int)col[i + j];
                if ((unsigned)c < (unsigned)n) atomicAdd(&g_cnt[c], 1);
            }
    } else {
        const int* col = (const int*)ei + e;
        if (i + 3 < e) {
            int4 c4 = *(const int4*)(col + i);
            if ((unsigned)c4.x < (unsigned)n) atomicAdd(&g_cnt[c4.x], 1);
            if ((unsigned)c4.y < (unsigned)n) atomicAdd(&g_cnt[c4.y], 1);
            if ((unsigned)c4.z < (unsigned)n) atomicAdd(&g_cnt[c4.z], 1);
            if ((unsigned)c4.w < (unsigned)n) atomicAdd(&g_cnt[c4.w], 1);
        } else {
            for (int j = 0; j < 4 && i + j < e; j++) {
                int c = col[i + j];
                if ((unsigned)c < (unsigned)n) atomicAdd(&g_cnt[c], 1);
            }
        }
    }
}

// per-1024-chunk sums; 256 threads, int4 per thread.
__global__ void k_scan_a(int n) {
    __shared__ int wsum[8];
    int t = threadIdx.x;
    int i = blockIdx.x * 1024 + t * 4;
    int v = 0;
    if (i + 3 < n) {
        int4 c = *(const int4*)&g_cnt[i];
        v = c.x + c.y + c.z + c.w;
    } else {
        for (int j = 0; j < 4 && i + j < n; j++) v += g_cnt[i + j];
    }
#pragma unroll
    for (int s = 16; s > 0; s >>= 1) v += __shfl_down_sync(0xffffffffu, v, s);
    if ((t & 31) == 0) wsum[t >> 5] = v;
    __syncthreads();
    if (t < 32) {
        int x = (t < 8) ? wsum[t] : 0;
#pragma unroll
        for (int s = 4; s > 0; s >>= 1) x += __shfl_down_sync(0xffffffffu, x, s);
        if (t == 0) g_bsum[blockIdx.x] = x;
    }
}

// Per-block scan; block offset computed in-kernel from g_bsum.
__global__ void k_scan_c(int n, int e) {
    __shared__ int wsum[32];
    __shared__ int wpre[32];
    __shared__ int blockOff;
    int t = threadIdx.x, lane = t & 31, wid = t >> 5;
    int i = blockIdx.x * 1024 + t;
    if (t < 32) {
        int s = 0;
        for (int j = t; j < blockIdx.x; j += 32) s += g_bsum[j];
#pragma unroll
        for (int d = 16; d > 0; d >>= 1) s += __shfl_down_sync(0xffffffffu, s, d);
        if (t == 0) blockOff = s;
    }
    int v = (i < n) ? g_cnt[i] : 0;
    int incl = v;
#pragma unroll
    for (int d = 1; d < 32; d <<= 1) {
        int u = __shfl_up_sync(0xffffffffu, incl, d);
        if (lane >= d) incl += u;
    }
    if (lane == 31) wsum[wid] = incl;
    __syncthreads();
    if (t < 32) {
        int x = wsum[t];
        int xi = x;
#pragma unroll
        for (int d = 1; d < 32; d <<= 1) {
            int u = __shfl_up_sync(0xffffffffu, xi, d);
            if (t >= d) xi += u;
        }
        wpre[t] = xi - x;
    }
    __syncthreads();
    if (i < n) {
        int off = blockOff + wpre[wid] + incl - v;  // exclusive
        g_off[i] = off;
        g_cur[i] = off;
        g_dinv[i] = rsqrtf((float)(v + 1));         // +1 self loop
    }
    if (i == 0) g_off[n] = e;
}

__global__ void k_fill(const void* __restrict__ ei, int e, int n) {
    __shared__ int sIs64;
    int tid = threadIdx.x;
    if (tid == 0) sIs64 = 1;
    __syncthreads();
    if (tid < 64 && ((const unsigned int*)ei)[2 * tid + 1] != 0u) sIs64 = 0;
    __syncthreads();
    int is64 = sIs64;

    int i = (blockIdx.x * blockDim.x + tid) * 4;
    if (i >= e) return;
    int r[4], c[4], m = (e - i < 4) ? (e - i) : 4;
    if (is64) {
        const long long* row = (const long long*)ei;
        const long long* col = row + e;
        for (int j = 0; j < m; j++) { r[j] = (int)row[i + j]; c[j] = (int)col[i + j]; }
    } else {
        const int* row = (const int*)ei;
        const int* col = row + e;
        if (m == 4) {
            int4 r4 = *(const int4*)(row + i);
            int4 c4 = *(const int4*)(col + i);
            r[0] = r4.x; r[1] = r4.y; r[2] = r4.z; r[3] = r4.w;
            c[0] = c4.x; c[1] = c4.y; c[2] = c4.z; c[3] = c4.w;
        } else {
            for (int j = 0; j < m; j++) { r[j] = row[i + j]; c[j] = col[i + j]; }
        }
    }
    for (int j = 0; j < m; j++) {
        if ((unsigned)c[j] < (unsigned)n && (unsigned)r[j] < (unsigned)n) {
            int p = atomicAdd(&g_cur[c[j]], 1);
            if (p < e) g_rows[p] = r[j];
        }
    }
}

// h1s[n][f] = (x[n] . W1[:,f]) * dinv[n], stored as half2 pairs.
__global__ void k_gemm1(const float* __restrict__ x,
                        const float* __restrict__ W1, int n) {
    __shared__ __align__(16) float Ws[INF_ * HID_];   // 8 KB, [k][f]
    __shared__ float Xs[128 * 65];
    int tid = threadIdx.x;
    int fg = tid >> 6;          // 0..3  (features fg*4 .. fg*4+3)
    int q  = tid & 63;
    int base = blockIdx.x * 128;

    for (int i = tid; i < INF_ * HID_; i += 256) Ws[i] = W1[i];

    float4 a0 = {0.f, 0.f, 0.f, 0.f};
    float4 a1 = {0.f, 0.f, 0.f, 0.f};

    for (int kc = 0; kc < 2; kc++) {
        __syncthreads();
        for (int idx = tid; idx < 128 * 16; idx += 256) {
            int row = idx >> 4, c4 = idx & 15;
            int node = base + row;
            float4 v = {0.f, 0.f, 0.f, 0.f};
            if (node < n) v = *(const float4*)&x[node * INF_ + kc * 64 + c4 * 4];
            float* dst = &Xs[row * 65 + c4 * 4];
            dst[0] = v.x; dst[1] = v.y; dst[2] = v.z; dst[3] = v.w;
        }
        __syncthreads();
#pragma unroll 8
        for (int k = 0; k < 64; k++) {
            float xv0 = Xs[q * 65 + k];
            float xv1 = Xs[(q + 64) * 65 + k];
            float4 w4 = *(const float4*)&Ws[(kc * 64 + k) * HID_ + fg * 4];
            a0.x = fmaf(xv0, w4.x, a0.x); a0.y = fmaf(xv0, w4.y, a0.y);
            a0.z = fmaf(xv0, w4.z, a0.z); a0.w = fmaf(xv0, w4.w, a0.w);
            a1.x = fmaf(xv1, w4.x, a1.x); a1.y = fmaf(xv1, w4.y, a1.y);
            a1.z = fmaf(xv1, w4.z, a1.z); a1.w = fmaf(xv1, w4.w, a1.w);
        }
    }
    int n0 = base + q, n1 = base + q + 64;
    if (n0 < n) {
        float d = g_dinv[n0];
        g_h1s[n0 * 8 + fg * 2]     = __floats2half2_rn(a0.x * d, a0.y * d);
        g_h1s[n0 * 8 + fg * 2 + 1] = __floats2half2_rn(a0.z * d, a0.w * d);
    }
    if (n1 < n) {
        float d = g_dinv[n1];
        g_h1s[n1 * 8 + fg * 2]     = __floats2half2_rn(a1.x * d, a1.y * d);
        g_h1s[n1 * 8 + fg * 2 + 1] = __floats2half2_rn(a1.z * d, a1.w * d);
    }
}

// Layer-1 aggregate + relu, pre-scaled for layer 2.
// Warp per node. Indices fetched 32-at-a-time with ONE coalesced load, then
// SHFL-broadcast to the 4 edge-groups -> gathers are independent (MLP~8).
__global__ void k_agg1f(const float* __restrict__ b1, int n) {
    int tid = threadIdx.x, lane = tid & 31, w = tid >> 5;
    int eg = lane >> 3, tA = lane & 7;
    int node = blockIdx.x * 8 + w;
    if (node >= n) return;
    int e0 = g_off[node], cnt = g_off[node + 1] - e0;
    float2 s = {0.f, 0.f};
    if (eg == 0) s = __half22float2(g_h1s[node * 8 + tA]);   // self loop
    for (int base = 0; base < cnt; base += 32) {
        int rem = cnt - base; if (rem > 32) rem = 32;
        int idx = 0;
        if (lane < rem) idx = __ldg(&g_rows[e0 + base + lane]);
#pragma unroll
        for (int u = 0; u < 8; u++) {
            int i = eg + 4 * u;
            int r = __shfl_sync(0xffffffffu, idx, i);
            if (i < rem) {
                float2 v = __half22float2(g_h1s[r * 8 + tA]);
                s.x += v.x; s.y += v.y;
            }
        }
    }
    s.x += __shfl_xor_sync(0xffffffffu, s.x, 8);
    s.y += __shfl_xor_sync(0xffffffffu, s.y, 8);
    s.x += __shfl_xor_sync(0xffffffffu, s.x, 16);
    s.y += __shfl_xor_sync(0xffffffffu, s.y, 16);
    if (lane < 8) {
        float d = g_dinv[node];
        float2 bb = ((const float2*)b1)[tA];
        float ox = fmaxf(fmaf(s.x, d, bb.x), 0.f) * d;
        float oy = fmaxf(fmaf(s.y, d, bb.y), 0.f) * d;
        g_o1s[node * 8 + tA] = __floats2half2_rn(ox, oy);
    }
}

// Layer-2 fully fused: 16-dim aggregate (A commutes with W2), 16->64 GEMM +
// bias + relu into the global pool; last block does the epilogue and restores
// persistent state (g_cnt per node, g_Sacc, g_done).
__global__ void k_agg2f(const float* __restrict__ b2,
                        const float* __restrict__ W2,
                        const float* __restrict__ fcW,
                        const float* __restrict__ fcb,
                        float* __restrict__ out, int n) {
    __shared__ __align__(16) float Ws[HID_ * NC_];   // 4 KB, [j][k]
    __shared__ float A16[8 * 17];
    __shared__ float red[8 * 66];
    int tid = threadIdx.x, lane = tid & 31, w = tid >> 5;
    for (int i = tid; i < HID_ * NC_; i += 256) Ws[i] = W2[i];

    int eg = lane >> 3, tA = lane & 7;       // phase-A mapping
    int wB = tid >> 5, cB = tid & 31;        // phase-B: node slot, col pair
    float2 bb = ((const float2*)b2)[cB];
    float2 acc = {0.f, 0.f};

    int ntiles = (n + 7) / 8;

    for (int tile = blockIdx.x; tile < ntiles; tile += gridDim.x) {
        __syncthreads();                     // protect A16 reuse
        int node = tile * 8 + w;
        if (node < n) {
            if (lane == 0) g_cnt[node] = 0;  // restore for next run
            int e0 = g_off[node], cnt = g_off[node + 1] - e0;
            float2 s = {0.f, 0.f};
            if (eg == 0) s = __half22float2(g_o1s[node * 8 + tA]);
            for (int base = 0; base < cnt; base += 32) {
                int rem = cnt - base; if (rem > 32) rem = 32;
                int idx = 0;
                if (lane < rem) idx = __ldg(&g_rows[e0 + base + lane]);
#pragma unroll
                for (int u = 0; u < 8; u++) {
                    int i = eg + 4 * u;
                    int r = __shfl_sync(0xffffffffu, idx, i);
                    if (i < rem) {
                        float2 v = __half22float2(g_o1s[r * 8 + tA]);
                        s.x += v.x; s.y += v.y;
                    }
                }
            }
            s.x += __shfl_xor_sync(0xffffffffu, s.x, 8);
            s.y += __shfl_xor_sync(0xffffffffu, s.y, 8);
            s.x += __shfl_xor_sync(0xffffffffu, s.x, 16);
            s.y += __shfl_xor_sync(0xffffffffu, s.y, 16);
            if (lane < 8) {
                float d = g_dinv[node];
                A16[w * 17 + 2 * tA]     = s.x * d;
                A16[w * 17 + 2 * tA + 1] = s.y * d;
            }
        }
        __syncthreads();
        int node2 = tile * 8 + wB;
        if (node2 < n) {
            float2 p = bb;
#pragma unroll
            for (int j = 0; j < HID_; j++) {
                float o = A16[wB * 17 + j];
                float2 w2 = *(const float2*)&Ws[j * NC_ + 2 * cB];
                p.x = fmaf(o, w2.x, p.x);
                p.y = fmaf(o, w2.y, p.y);
            }
            acc.x += fmaxf(p.x, 0.f);
            acc.y += fmaxf(p.y, 0.f);
        }
    }

    // block-level pool reduce
    __syncthreads();
    red[wB * 66 + 2 * cB]     = acc.x;
    red[wB * 66 + 2 * cB + 1] = acc.y;
    __syncthreads();
    if (tid < 64) {
        float tot = 0.f;
#pragma unroll
        for (int i = 0; i < 8; i++) tot += red[i * 66 + tid];
        atomicAdd(&g_Sacc[tid * 64], tot);
    }

    // last block computes the epilogue and restores g_Sacc / g_done
    __threadfence();
    __shared__ int amLast;
    if (tid == 0) amLast = (atomicAdd(&g_done, 1) == gridDim.x - 1);
    __syncthreads();
    if (amLast && tid == 0) {
        float nf = (float)n;
        float p0 = nf * fcb[0], p1 = nf * fcb[1];
        for (int k = 0; k < NC_; k++) {
            float sv = g_Sacc[k * 64];
            g_Sacc[k * 64] = 0.f;
            p0 = fmaf(sv, fcW[k * 2 + 0], p0);
            p1 = fmaf(sv, fcW[k * 2 + 1], p1);
        }
        g_done = 0;
        float m = fmaxf(p0, p1);
        float l = m + logf(expf(p0 - m) + expf(p1 - m));
        out[0] = p0 - l;
        out[1] = p1 - l;
    }
}

// ---------------- launcher ----------------
extern "C" void kernel_launch(void* const* d_in, const int* in_sizes, int n_in,
                              void* d_out, int out_size) {
    const float* x   = (const float*)d_in[0];
    const void*  ei  = (const void*)d_in[1];
    const float* W1  = (const float*)d_in[2];
    const float* b1  = (const float*)d_in[3];
    const float* W2  = (const float*)d_in[4];
    const float* b2  = (const float*)d_in[5];
    const float* fcW = (const float*)d_in[6];
    const float* fcb = (const float*)d_in[7];
    float* out = (float*)d_out;

    int n = in_sizes[0] / INF_;   // 100000
    int e = in_sizes[1] / 2;      // 3200000
    if (n > NN) n = NN;
    if (e > EE) e = EE;

    int nbScan  = (n + 1023) / 1024;
    int nbEdge4 = (e + 1023) / 1024;

    k_count <<<nbEdge4, 256>>>(ei, e, n);
    k_scan_a<<<nbScan, 256>>>(n);
    k_scan_c<<<nbScan, 1024>>>(n, e);
    k_fill  <<<nbEdge4, 256>>>(ei, e, n);
    k_gemm1 <<<(n + 127) / 128, 256>>>(x, W1, n);
    k_agg1f <<<(n + 7) / 8, 256>>>(b1, n);
    k_agg2f <<<1184, 256>>>(b2, W2, fcW, fcb, out, n);
}